// round 14
// baseline (speedup 1.0000x reference)
#include <cuda_runtime.h>
#include <cuda_fp16.h>
#include <cstdint>

// SplitContextCenterConv2D as implicit GEMM on warp-level fp16 mma.sync.
// GEMM: M = 8*256*256 pixels, N = 256, K = 1152 (36 chunks of 32).
// CTA tile 128x128, 2 CTAs/SM, full unroll, 1 barrier/chunk.
// This round: ldmatrix.x4 fragment loads (12 instr/warp-chunk vs 48 LDS.64),
// 80B row stride -> conflict-free ldmatrix phases, natural k order.

#define HH 256
#define WW 256
#define CIN 128
#define COUT 256
#define KTOT 1152
#define NCHUNK 36

#define ROWB 80                        // bytes per smem row (64B data + 16B pad)
#define A_BYTES (128 * ROWB)           // 10240
#define STAGE_BYTES (2 * A_BYTES)      // 20480 (A + B)
#define SMEM_BYTES (2 * STAGE_BYTES)   // 40960

__device__ __half g_wt16[COUT * KTOT];   // fp16 weights, layout [n][k]

__global__ void wt_transform(const float* __restrict__ kern) {
    int o = blockIdx.x * 256 + threadIdx.x;
    if (o >= COUT * KTOT) return;
    int n = o / KTOT;
    int k = o - n * KTOT;
    int t = k >> 7;
    int ci = k & 127;
    int io = (t == 4) ? 1 : 0;
    float v = kern[(size_t)((t * 2 + io) * CIN + ci) * COUT + n];
    g_wt16[o] = __float2half_rn(v);
}

static __device__ __forceinline__ void cp16(uint32_t dst, const void* src) {
    asm volatile("cp.async.cg.shared.global [%0], [%1], 16;"
                 :: "r"(dst), "l"(src) : "memory");
}
static __device__ __forceinline__ uint32_t pack_h2(float lo, float hi) {
    uint32_t r;
    asm("cvt.rn.f16x2.f32 %0, %1, %2;" : "=r"(r) : "f"(hi), "f"(lo));
    return r;
}
static __device__ __forceinline__ void ldm4(uint32_t addr, uint32_t* r) {
    asm volatile("ldmatrix.sync.aligned.m8n8.x4.shared.b16 {%0,%1,%2,%3}, [%4];"
                 : "=r"(r[0]), "=r"(r[1]), "=r"(r[2]), "=r"(r[3]) : "r"(addr));
}

__global__ __launch_bounds__(256, 2)
void conv_mma(const float* __restrict__ x, const float* __restrict__ bias,
              float* __restrict__ out) {
    extern __shared__ char smem[];
    const uint32_t smem_b = (uint32_t)__cvta_generic_to_shared(smem);

    const int tid  = threadIdx.x;
    const int wid  = tid >> 5;
    const int lane = tid & 31;
    const int g    = lane >> 2;   // 0..7
    const int tig  = lane & 3;    // 0..3
    const int quad = lane >> 3;   // 0..3 (ldmatrix address group)
    const int lr   = lane & 7;

    const int m0 = (wid & 1) * 64;   // warp M offset
    const int n0 = (wid >> 1) * 32;  // warp N offset

    const int b  = blockIdx.z;
    const int h  = blockIdx.y;
    const int w0 = (blockIdx.x >> 1) * 128;
    const int nb = (blockIdx.x & 1) * 128;      // N half
    const size_t img = (size_t)b * HH * WW * COUT;

    // ---------------- hoisted invariants ----------------
    const int mbase = tid >> 3;          // 0..31 (+32 per i)
    const int jk    = tid & 7;           // k segment (4 floats / 4 fp16)

    int offC[4];                          // central (kx==1) gmem offsets
#pragma unroll
    for (int i = 0; i < 4; i++) offC[i] = (w0 + mbase + 32 * i) * COUT + jk * 4;
    const int gwL0 = w0 + mbase - 1;
    const bool okL0 = (gwL0 >= 0);
    const int offL0 = (okL0 ? gwL0 : 0) * COUT + jk * 4;
    const int gwR3 = w0 + mbase + 97;
    const bool okR3 = (gwR3 < WW);
    const int offR3 = (okR3 ? gwR3 : WW - 1) * COUT + jk * 4;

    const float* rowPtr[3];
    bool rowOk[3];
#pragma unroll
    for (int r = 0; r < 3; r++) {
        int gh = h - 1 + r;
        rowOk[r] = (unsigned)gh < (unsigned)HH;
        rowPtr[r] = x + img + (size_t)(rowOk[r] ? gh : 0) * WW * COUT;
    }

    // A smem dst byte offsets
    uint32_t sdA[4];
#pragma unroll
    for (int i = 0; i < 4; i++)
        sdA[i] = (uint32_t)((mbase + 32 * i) * ROWB + jk * 8);

    // B cp.async: 2 segs/thread
    const int bRow0 = tid >> 2;
    const int bSeg  = tid & 3;
    uint32_t sdB[2];
    int bOff[2];
#pragma unroll
    for (int i = 0; i < 2; i++) {
        int row = bRow0 + 64 * i;
        sdB[i] = (uint32_t)(A_BYTES + row * ROWB + bSeg * 16);
        bOff[i] = (nb + row) * KTOT + bSeg * 8;
    }

    // ldmatrix lane addresses (byte offsets within stage)
    // A (x4 -> a0..a3): quads: (m+0..7,k0) (m+8..15,k0) (m+0..7,k8) (m+8..15,k8)
    uint32_t lmA[4];
#pragma unroll
    for (int mi = 0; mi < 4; mi++)
        lmA[mi] = (uint32_t)((m0 + mi * 16 + (quad & 1) * 8 + lr) * ROWB
                             + (quad >> 1) * 16);
    // B (x4 -> b0,b1 for two n8 tiles): quads: (n+0..7,k0) (n+0..7,k8)
    //                                          (n+8..15,k0) (n+8..15,k8)
    uint32_t lmB[2];
#pragma unroll
    for (int n2 = 0; n2 < 2; n2++)
        lmB[n2] = (uint32_t)(A_BYTES + (n0 + n2 * 16 + (quad >> 1) * 8 + lr) * ROWB
                             + (quad & 1) * 16);

    float acc[4][4][4];
#pragma unroll
    for (int mi = 0; mi < 4; mi++)
#pragma unroll
        for (int ni = 0; ni < 4; ni++)
#pragma unroll
            for (int r = 0; r < 4; r++) acc[mi][ni][r] = 0.f;

    float4 va[4];   // in-flight A data for next chunk

    auto ldgA = [&](int c) {
        const int t   = c >> 2;
        const int ci0 = (c & 3) << 5;
        const bool cen = (t == 4);
        const int ky = t / 3, kx = t % 3;
        const float* base = cen ? (rowPtr[1] + CIN + ci0) : (rowPtr[ky] + ci0);
        const bool rok = cen ? true : rowOk[ky];
#pragma unroll
        for (int i = 0; i < 4; i++) {
            int off; bool ok;
            if (cen || kx == 1) { off = offC[i]; ok = rok; }
            else if (kx == 0) {
                off = (i == 0) ? offL0 : (offC[i] - COUT);
                ok  = (i == 0) ? (okL0 && rok) : rok;
            } else {
                off = (i == 3) ? offR3 : (offC[i] + COUT);
                ok  = (i == 3) ? (okR3 && rok) : rok;
            }
            va[i] = make_float4(0.f, 0.f, 0.f, 0.f);
            if (ok) va[i] = *(const float4*)(base + off);
        }
    };
    auto cpB = [&](int c) {
        const uint32_t st = smem_b + (uint32_t)((c & 1) * STAGE_BYTES);
        const __half* wbase = g_wt16 + c * 32;
#pragma unroll
        for (int i = 0; i < 2; i++)
            cp16(st + sdB[i], wbase + bOff[i]);
        asm volatile("cp.async.commit_group;" ::: "memory");
    };
    auto stsA = [&](int c) {
        const uint32_t st = smem_b + (uint32_t)((c & 1) * STAGE_BYTES);
#pragma unroll
        for (int i = 0; i < 4; i++) {
            uint32_t h0 = pack_h2(va[i].x, va[i].y);
            uint32_t h1 = pack_h2(va[i].z, va[i].w);
            asm volatile("st.shared.v2.b32 [%0], {%1, %2};"
                         :: "r"(st + sdA[i]), "r"(h0), "r"(h1) : "memory");
        }
    };

    // prologue: fill stage 0
    ldgA(0); cpB(0); stsA(0);
    asm volatile("cp.async.wait_group 0;" ::: "memory");
    __syncthreads();

#pragma unroll
    for (int c = 0; c < NCHUNK; c++) {
        if (c + 1 < NCHUNK) { ldgA(c + 1); cpB(c + 1); }

        const uint32_t st = smem_b + (uint32_t)((c & 1) * STAGE_BYTES);

#pragma unroll
        for (int ks = 0; ks < 2; ks++) {
            uint32_t aF[4][4];
#pragma unroll
            for (int mi = 0; mi < 4; mi++)
                ldm4(st + lmA[mi] + ks * 32, aF[mi]);
            uint32_t bF[2][4];
#pragma unroll
            for (int n2 = 0; n2 < 2; n2++)
                ldm4(st + lmB[n2] + ks * 32, bF[n2]);
#pragma unroll
            for (int mi = 0; mi < 4; mi++)
#pragma unroll
                for (int ni = 0; ni < 4; ni++) {
                    const uint32_t* bp = &bF[ni >> 1][(ni & 1) * 2];
                    asm volatile(
                        "mma.sync.aligned.m16n8k16.row.col.f32.f16.f16.f32 "
                        "{%0,%1,%2,%3}, {%4,%5,%6,%7}, {%8,%9}, {%0,%1,%2,%3};"
                        : "+f"(acc[mi][ni][0]), "+f"(acc[mi][ni][1]),
                          "+f"(acc[mi][ni][2]), "+f"(acc[mi][ni][3])
                        : "r"(aF[mi][0]), "r"(aF[mi][1]),
                          "r"(aF[mi][2]), "r"(aF[mi][3]),
                          "r"(bp[0]), "r"(bp[1]));
                }
        }

        if (c + 1 < NCHUNK) stsA(c + 1);
        asm volatile("cp.async.wait_group 0;" ::: "memory");
        __syncthreads();
    }

    // ---------------- epilogue ----------------
    float bv[4][2];
#pragma unroll
    for (int ni = 0; ni < 4; ni++) {
        int n = nb + n0 + ni * 8 + tig * 2;
        bv[ni][0] = bias[n];
        bv[ni][1] = bias[n + 1];
    }
#pragma unroll
    for (int mi = 0; mi < 4; mi++) {
        int r0 = m0 + mi * 16 + g;
        float* p0 = out + img + ((size_t)h * WW + (w0 + r0)) * COUT;
        float* p1 = out + img + ((size_t)h * WW + (w0 + r0 + 8)) * COUT;
#pragma unroll
        for (int ni = 0; ni < 4; ni++) {
            int n = nb + n0 + ni * 8 + tig * 2;
            float2 v0 = make_float2(acc[mi][ni][0] + bv[ni][0],
                                    acc[mi][ni][1] + bv[ni][1]);
            float2 v1 = make_float2(acc[mi][ni][2] + bv[ni][0],
                                    acc[mi][ni][3] + bv[ni][1]);
            *(float2*)(p0 + n) = v0;
            *(float2*)(p1 + n) = v1;
        }
    }
}

extern "C" void kernel_launch(void* const* d_in, const int* in_sizes, int n_in,
                              void* d_out, int out_size) {
    (void)in_sizes; (void)n_in; (void)out_size;
    const float* x    = (const float*)d_in[0];
    const float* kern = (const float*)d_in[1];
    const float* bias = (const float*)d_in[2];
    float* out = (float*)d_out;

    wt_transform<<<(COUT * KTOT + 255) / 256, 256>>>(kern);

    cudaFuncSetAttribute(conv_mma, cudaFuncAttributeMaxDynamicSharedMemorySize, SMEM_BYTES);
    dim3 grid((WW / 128) * (COUT / 128), HH, 8);   // (4, 256, 8) = 8192 CTAs
    conv_mma<<<grid, 256, SMEM_BYTES>>>(x, bias, out);
}

// round 15
// speedup vs baseline: 1.0654x; 1.0654x over previous
#include <cuda_runtime.h>
#include <cuda_fp16.h>
#include <cstdint>

// SplitContextCenterConv2D as implicit GEMM on warp-level fp16 mma.sync.
// GEMM: M = 8*256*256 pixels, N = 256, K = 1152.
// This round: spatial halo reuse. Per ci-chunk (32 ci), load ONE halo tile
// (3 rows x 130 px ctx + 128 px center) into smem; all 9 taps read shifted
// windows via compile-time row offsets. Producer gmem/smem traffic /~6.
// B double-buffered per (ci,tap); consumer = round-13 LDS.64 k-slot scheme.

#define HH 256
#define WW 256
#define CIN 128
#define COUT 256
#define KTOT 1152

#define ROWB 96                         // bytes per smem row (64B data + pad)
#define AROWS 518                       // 3*130 ctx halo rows + 128 center
#define A_BYTES (AROWS * ROWB)          // 49728
#define B_OFF A_BYTES
#define B_STAGE (128 * ROWB)            // 12288
#define SMEM_BYTES (A_BYTES + 2 * B_STAGE)   // 74304

__device__ __half g_wt16[COUT * KTOT];  // fp16 weights, layout [n][k]

__global__ void wt_transform(const float* __restrict__ kern) {
    int o = blockIdx.x * 256 + threadIdx.x;
    if (o >= COUT * KTOT) return;
    int n = o / KTOT;
    int k = o - n * KTOT;
    int t = k >> 7;
    int ci = k & 127;
    int io = (t == 4) ? 1 : 0;
    float v = kern[(size_t)((t * 2 + io) * CIN + ci) * COUT + n];
    g_wt16[o] = __float2half_rn(v);
}

static __device__ __forceinline__ void cp16(uint32_t dst, const void* src) {
    asm volatile("cp.async.cg.shared.global [%0], [%1], 16;"
                 :: "r"(dst), "l"(src) : "memory");
}
static __device__ __forceinline__ uint32_t pack_h2(float lo, float hi) {
    uint32_t r;
    asm("cvt.rn.f16x2.f32 %0, %1, %2;" : "=r"(r) : "f"(hi), "f"(lo));
    return r;
}

__global__ __launch_bounds__(256, 2)
void conv_mma(const float* __restrict__ x, const float* __restrict__ bias,
              float* __restrict__ out) {
    extern __shared__ char smem[];
    const uint32_t smem_b = (uint32_t)__cvta_generic_to_shared(smem);

    const int tid  = threadIdx.x;
    const int wid  = tid >> 5;
    const int lane = tid & 31;
    const int g    = lane >> 2;   // 0..7
    const int tig  = lane & 3;    // 0..3

    const int m0 = (wid & 1) * 64;   // warp M offset
    const int n0 = (wid >> 1) * 32;  // warp N offset

    const int b  = blockIdx.z;
    const int h  = blockIdx.y;
    const int w0 = (blockIdx.x >> 1) * 128;
    const int nb = (blockIdx.x & 1) * 128;      // N half
    const size_t img = (size_t)b * HH * WW * COUT;
    const float* xb = x + img;

    // ---------------- producer A invariants: 9 segment slots ----------------
    // ctx slots s=0..6: e = tid+256s (<1560): row = e>>2 in [0,390), seg = e&3.
    //   row = rb*130 + px, pixel gw = w0-1+px, source row gh = h-1+rb.
    // center slots s=7,8: rows 390+[0,128), channels 128+cc*32.
    uint32_t aDst[9], aSrc[9];
    bool aOk[9];
#pragma unroll
    for (int s = 0; s < 7; s++) {
        int e = tid + 256 * s;
        int row = e >> 2, seg = e & 3;
        int rb = row / 130;
        int px = row - rb * 130;
        int gh = h - 1 + rb;
        int gw = w0 - 1 + px;
        bool ok = (e < 1560) && ((unsigned)gh < (unsigned)HH) &&
                  ((unsigned)gw < (unsigned)WW);
        aDst[s] = (uint32_t)(row * ROWB + seg * 16);
        aSrc[s] = ok ? (uint32_t)((gh * WW + gw) * COUT + seg * 8) : 0u;
        aOk[s] = ok;
    }
#pragma unroll
    for (int s = 7; s < 9; s++) {
        int row = (tid >> 2) + 64 * (s - 7);
        int seg = tid & 3;
        aDst[s] = (uint32_t)((390 + row) * ROWB + seg * 16);
        aSrc[s] = (uint32_t)((h * WW + w0 + row) * COUT + CIN + seg * 8);
        aOk[s] = true;
    }
    const bool sv6 = (tid < 24);    // slot-6 store predicate (e<1560)

    auto prodA = [&](int cc) {
#pragma unroll
        for (int s = 0; s < 9; s++) {
            if (s == 6 && !sv6) continue;
            float4 v0 = make_float4(0.f, 0.f, 0.f, 0.f);
            float4 v1 = v0;
            if (aOk[s]) {
                const float* p = xb + aSrc[s] + cc * 32;
                v0 = *(const float4*)p;
                v1 = *(const float4*)(p + 4);
            }
            uint32_t h0 = pack_h2(v0.x, v0.y), h1 = pack_h2(v0.z, v0.w);
            uint32_t h2 = pack_h2(v1.x, v1.y), h3 = pack_h2(v1.z, v1.w);
            asm volatile("st.shared.v4.b32 [%0], {%1,%2,%3,%4};"
                         :: "r"(smem_b + aDst[s]),
                            "r"(h0), "r"(h1), "r"(h2), "r"(h3) : "memory");
        }
    };

    // ---------------- B invariants ----------------
    const int bRow0 = tid >> 2, bSeg = tid & 3;
    uint32_t sdB[2], bOff[2];
#pragma unroll
    for (int i = 0; i < 2; i++) {
        int row = bRow0 + 64 * i;
        sdB[i] = (uint32_t)(B_OFF + row * ROWB + bSeg * 16);
        bOff[i] = (uint32_t)((nb + row) * KTOT + bSeg * 8);
    }
    auto cpB = [&](int ic) {           // ic compile-time after unroll
        int cc2 = ic / 9, t2 = ic - cc2 * 9;
        uint32_t st = smem_b + (uint32_t)((ic & 1) * B_STAGE);
        const __half* wb = g_wt16 + t2 * 128 + cc2 * 32;
        cp16(st + sdB[0], wb + bOff[0]);
        cp16(st + sdB[1], wb + bOff[1]);
        asm volatile("cp.async.commit_group;" ::: "memory");
    };

    // ---------------- fragment invariants ----------------
    uint32_t fA[4], fB[4];
#pragma unroll
    for (int mi = 0; mi < 4; mi++)
        fA[mi] = (uint32_t)((m0 + mi * 16 + g) * ROWB + tig * 8);
#pragma unroll
    for (int ni = 0; ni < 4; ni++)
        fB[ni] = (uint32_t)(B_OFF + (n0 + ni * 8 + g) * ROWB + tig * 8);

    float acc[4][4][4];
#pragma unroll
    for (int mi = 0; mi < 4; mi++)
#pragma unroll
        for (int ni = 0; ni < 4; ni++)
#pragma unroll
            for (int r = 0; r < 4; r++) acc[mi][ni][r] = 0.f;

    // ---------------- prologue ----------------
    prodA(0);
    cpB(0);
    asm volatile("cp.async.wait_group 0;" ::: "memory");
    __syncthreads();

    // ---------------- main: 4 ci-chunks x 9 taps ----------------
#pragma unroll
    for (int cc = 0; cc < 4; cc++) {
#pragma unroll
        for (int t = 0; t < 9; t++) {
            const int ic = cc * 9 + t;
            if (ic + 1 < 36) cpB(ic + 1);

            // tap window: ctx taps read rows (ky*130 + kx + m); center reads
            // rows 390+m. Compile-time immediate per tap.
            const uint32_t tapOff = (t == 4)
                ? (uint32_t)(390 * ROWB)
                : (uint32_t)(((t / 3) * 130 + (t % 3)) * ROWB);
            const uint32_t bSt = (uint32_t)((ic & 1) * B_STAGE);

            // k-slot pairing (round-13 scheme): smem pos 4q,4q+1 -> MMA slots
            // 2q,2q+1; 4q+2,4q+3 -> 2q+8,2q+9, identical on A and B.
#pragma unroll
            for (int ks = 0; ks < 2; ks++) {
                uint32_t aF[4][4];
#pragma unroll
                for (int mi = 0; mi < 4; mi++) {
                    asm volatile("ld.shared.v2.b32 {%0, %1}, [%2];"
                                 : "=r"(aF[mi][0]), "=r"(aF[mi][2])
                                 : "r"(smem_b + fA[mi] + tapOff + ks * 32));
                    asm volatile("ld.shared.v2.b32 {%0, %1}, [%2];"
                                 : "=r"(aF[mi][1]), "=r"(aF[mi][3])
                                 : "r"(smem_b + fA[mi] + tapOff + 8 * ROWB + ks * 32));
                }
                uint32_t bF[4][2];
#pragma unroll
                for (int ni = 0; ni < 4; ni++)
                    asm volatile("ld.shared.v2.b32 {%0, %1}, [%2];"
                                 : "=r"(bF[ni][0]), "=r"(bF[ni][1])
                                 : "r"(smem_b + fB[ni] + bSt + ks * 32));
#pragma unroll
                for (int mi = 0; mi < 4; mi++)
#pragma unroll
                    for (int ni = 0; ni < 4; ni++)
                        asm volatile(
                            "mma.sync.aligned.m16n8k16.row.col.f32.f16.f16.f32 "
                            "{%0,%1,%2,%3}, {%4,%5,%6,%7}, {%8,%9}, {%0,%1,%2,%3};"
                            : "+f"(acc[mi][ni][0]), "+f"(acc[mi][ni][1]),
                              "+f"(acc[mi][ni][2]), "+f"(acc[mi][ni][3])
                            : "r"(aF[mi][0]), "r"(aF[mi][1]),
                              "r"(aF[mi][2]), "r"(aF[mi][3]),
                              "r"(bF[ni][0]), "r"(bF[ni][1]));
            }

            if (t == 8 && cc < 3) {
                __syncthreads();       // all readers done with A tile
                prodA(cc + 1);         // refill halo tile for next ci-chunk
            }
            asm volatile("cp.async.wait_group 0;" ::: "memory");
            __syncthreads();
        }
    }

    // ---------------- epilogue ----------------
    float bv[4][2];
#pragma unroll
    for (int ni = 0; ni < 4; ni++) {
        int n = nb + n0 + ni * 8 + tig * 2;
        bv[ni][0] = bias[n];
        bv[ni][1] = bias[n + 1];
    }
#pragma unroll
    for (int mi = 0; mi < 4; mi++) {
        int r0 = m0 + mi * 16 + g;
        float* p0 = out + img + ((size_t)h * WW + (w0 + r0)) * COUT;
        float* p1 = out + img + ((size_t)h * WW + (w0 + r0 + 8)) * COUT;
#pragma unroll
        for (int ni = 0; ni < 4; ni++) {
            int n = nb + n0 + ni * 8 + tig * 2;
            float2 v0 = make_float2(acc[mi][ni][0] + bv[ni][0],
                                    acc[mi][ni][1] + bv[ni][1]);
            float2 v1 = make_float2(acc[mi][ni][2] + bv[ni][0],
                                    acc[mi][ni][3] + bv[ni][1]);
            *(float2*)(p0 + n) = v0;
            *(float2*)(p1 + n) = v1;
        }
    }
}

extern "C" void kernel_launch(void* const* d_in, const int* in_sizes, int n_in,
                              void* d_out, int out_size) {
    (void)in_sizes; (void)n_in; (void)out_size;
    const float* x    = (const float*)d_in[0];
    const float* kern = (const float*)d_in[1];
    const float* bias = (const float*)d_in[2];
    float* out = (float*)d_out;

    wt_transform<<<(COUT * KTOT + 255) / 256, 256>>>(kern);

    cudaFuncSetAttribute(conv_mma, cudaFuncAttributeMaxDynamicSharedMemorySize, SMEM_BYTES);
    dim3 grid((WW / 128) * (COUT / 128), HH, 8);   // (4, 256, 8) = 8192 CTAs
    conv_mma<<<grid, 256, SMEM_BYTES>>>(x, bias, out);
}

// round 16
// speedup vs baseline: 1.1187x; 1.0500x over previous
#include <cuda_runtime.h>
#include <cuda_fp16.h>
#include <cstdint>

// SplitContextCenterConv2D as implicit GEMM on warp-level fp16 mma.sync.
// GEMM: M = 8*256*256 pixels, N = 256, K = 1152.
// This round: 64x64 warp tiles (8 warps, CTA tile 128x256 = full N) to cut
// consumer LDS duplication by 33%; halo-reuse A tile shared across all N.
// 1 CTA/SM (128 acc regs/thread), double-buffered B, 1 barrier/chunk.

#define HH 256
#define WW 256
#define CIN 128
#define COUT 256
#define KTOT 1152

#define ROWB 96                         // bytes per smem row (64B data + pad)
#define AROWS 518                       // 3*130 ctx halo rows + 128 center
#define A_BYTES (AROWS * ROWB)          // 49728
#define B_OFF A_BYTES
#define B_STAGE (256 * ROWB)            // 24576
#define SMEM_BYTES (A_BYTES + 2 * B_STAGE)   // 98880

__device__ __half g_wt16[COUT * KTOT];  // fp16 weights, layout [n][k]

__global__ void wt_transform(const float* __restrict__ kern) {
    int o = blockIdx.x * 256 + threadIdx.x;
    if (o >= COUT * KTOT) return;
    int n = o / KTOT;
    int k = o - n * KTOT;
    int t = k >> 7;
    int ci = k & 127;
    int io = (t == 4) ? 1 : 0;
    float v = kern[(size_t)((t * 2 + io) * CIN + ci) * COUT + n];
    g_wt16[o] = __float2half_rn(v);
}

static __device__ __forceinline__ void cp16(uint32_t dst, const void* src) {
    asm volatile("cp.async.cg.shared.global [%0], [%1], 16;"
                 :: "r"(dst), "l"(src) : "memory");
}
static __device__ __forceinline__ uint32_t pack_h2(float lo, float hi) {
    uint32_t r;
    asm("cvt.rn.f16x2.f32 %0, %1, %2;" : "=r"(r) : "f"(hi), "f"(lo));
    return r;
}

__global__ __launch_bounds__(256, 1)
void conv_mma(const float* __restrict__ x, const float* __restrict__ bias,
              float* __restrict__ out) {
    extern __shared__ char smem[];
    const uint32_t smem_b = (uint32_t)__cvta_generic_to_shared(smem);

    const int tid  = threadIdx.x;
    const int wid  = tid >> 5;
    const int lane = tid & 31;
    const int g    = lane >> 2;   // 0..7
    const int tig  = lane & 3;    // 0..3

    const int m0 = (wid & 1) * 64;   // warp M offset (2 warps over M=128)
    const int n0 = (wid >> 1) * 64;  // warp N offset (4 warps over N=256)

    const int b  = blockIdx.z;
    const int h  = blockIdx.y;
    const int w0 = blockIdx.x * 128;
    const size_t img = (size_t)b * HH * WW * COUT;
    const float* xb = x + img;

    // ---------------- producer A invariants: 9 segment slots ----------------
    uint32_t aDst[9], aSrc[9];
    bool aOk[9];
#pragma unroll
    for (int s = 0; s < 7; s++) {
        int e = tid + 256 * s;
        int row = e >> 2, seg = e & 3;
        int rb = row / 130;
        int px = row - rb * 130;
        int gh = h - 1 + rb;
        int gw = w0 - 1 + px;
        bool ok = (e < 1560) && ((unsigned)gh < (unsigned)HH) &&
                  ((unsigned)gw < (unsigned)WW);
        aDst[s] = (uint32_t)(row * ROWB + seg * 16);
        aSrc[s] = ok ? (uint32_t)((gh * WW + gw) * COUT + seg * 8) : 0u;
        aOk[s] = ok;
    }
#pragma unroll
    for (int s = 7; s < 9; s++) {
        int row = (tid >> 2) + 64 * (s - 7);
        int seg = tid & 3;
        aDst[s] = (uint32_t)((390 + row) * ROWB + seg * 16);
        aSrc[s] = (uint32_t)((h * WW + w0 + row) * COUT + CIN + seg * 8);
        aOk[s] = true;
    }
    const bool sv6 = (tid < 24);

    auto prodA = [&](int cc) {
#pragma unroll
        for (int s = 0; s < 9; s++) {
            if (s == 6 && !sv6) continue;
            float4 v0 = make_float4(0.f, 0.f, 0.f, 0.f);
            float4 v1 = v0;
            if (aOk[s]) {
                const float* p = xb + aSrc[s] + cc * 32;
                v0 = *(const float4*)p;
                v1 = *(const float4*)(p + 4);
            }
            uint32_t h0 = pack_h2(v0.x, v0.y), h1 = pack_h2(v0.z, v0.w);
            uint32_t h2 = pack_h2(v1.x, v1.y), h3 = pack_h2(v1.z, v1.w);
            asm volatile("st.shared.v4.b32 [%0], {%1,%2,%3,%4};"
                         :: "r"(smem_b + aDst[s]),
                            "r"(h0), "r"(h1), "r"(h2), "r"(h3) : "memory");
        }
    };

    // ---------------- B invariants: 256 rows x 4 segs = 4 per thread ----------
    const int bRow0 = tid >> 2, bSeg = tid & 3;
    uint32_t sdB[4], bOff[4];
#pragma unroll
    for (int i = 0; i < 4; i++) {
        int row = bRow0 + 64 * i;
        sdB[i] = (uint32_t)(B_OFF + row * ROWB + bSeg * 16);
        bOff[i] = (uint32_t)(row * KTOT + bSeg * 8);
    }
    auto cpB = [&](int ic) {           // ic compile-time after unroll
        int cc2 = ic / 9, t2 = ic - cc2 * 9;
        uint32_t st = smem_b + (uint32_t)((ic & 1) * B_STAGE);
        const __half* wb = g_wt16 + t2 * 128 + cc2 * 32;
#pragma unroll
        for (int i = 0; i < 4; i++)
            cp16(st + sdB[i], wb + bOff[i]);
        asm volatile("cp.async.commit_group;" ::: "memory");
    };

    // ---------------- fragment invariants ----------------
    uint32_t fA[4], fB[8];
#pragma unroll
    for (int mi = 0; mi < 4; mi++)
        fA[mi] = (uint32_t)((m0 + mi * 16 + g) * ROWB + tig * 8);
#pragma unroll
    for (int ni = 0; ni < 8; ni++)
        fB[ni] = (uint32_t)(B_OFF + (n0 + ni * 8 + g) * ROWB + tig * 8);

    float acc[4][8][4];
#pragma unroll
    for (int mi = 0; mi < 4; mi++)
#pragma unroll
        for (int ni = 0; ni < 8; ni++)
#pragma unroll
            for (int r = 0; r < 4; r++) acc[mi][ni][r] = 0.f;

    // ---------------- prologue ----------------
    prodA(0);
    cpB(0);
    asm volatile("cp.async.wait_group 0;" ::: "memory");
    __syncthreads();

    // ---------------- main: 4 ci-chunks x 9 taps ----------------
#pragma unroll
    for (int cc = 0; cc < 4; cc++) {
#pragma unroll
        for (int t = 0; t < 9; t++) {
            const int ic = cc * 9 + t;
            if (ic + 1 < 36) cpB(ic + 1);

            const uint32_t tapOff = (t == 4)
                ? (uint32_t)(390 * ROWB)
                : (uint32_t)(((t / 3) * 130 + (t % 3)) * ROWB);
            const uint32_t bSt = (uint32_t)((ic & 1) * B_STAGE);

            // k-slot pairing: smem pos 4q,4q+1 -> MMA slots 2q,2q+1;
            // 4q+2,4q+3 -> 2q+8,2q+9, identical on A and B.
#pragma unroll
            for (int ks = 0; ks < 2; ks++) {
                uint32_t aF[4][4];
#pragma unroll
                for (int mi = 0; mi < 4; mi++) {
                    asm volatile("ld.shared.v2.b32 {%0, %1}, [%2];"
                                 : "=r"(aF[mi][0]), "=r"(aF[mi][2])
                                 : "r"(smem_b + fA[mi] + tapOff + ks * 32));
                    asm volatile("ld.shared.v2.b32 {%0, %1}, [%2];"
                                 : "=r"(aF[mi][1]), "=r"(aF[mi][3])
                                 : "r"(smem_b + fA[mi] + tapOff + 8 * ROWB + ks * 32));
                }
                uint32_t bF[8][2];
#pragma unroll
                for (int ni = 0; ni < 8; ni++)
                    asm volatile("ld.shared.v2.b32 {%0, %1}, [%2];"
                                 : "=r"(bF[ni][0]), "=r"(bF[ni][1])
                                 : "r"(smem_b + fB[ni] + bSt + ks * 32));
#pragma unroll
                for (int mi = 0; mi < 4; mi++)
#pragma unroll
                    for (int ni = 0; ni < 8; ni++)
                        asm volatile(
                            "mma.sync.aligned.m16n8k16.row.col.f32.f16.f16.f32 "
                            "{%0,%1,%2,%3}, {%4,%5,%6,%7}, {%8,%9}, {%0,%1,%2,%3};"
                            : "+f"(acc[mi][ni][0]), "+f"(acc[mi][ni][1]),
                              "+f"(acc[mi][ni][2]), "+f"(acc[mi][ni][3])
                            : "r"(aF[mi][0]), "r"(aF[mi][1]),
                              "r"(aF[mi][2]), "r"(aF[mi][3]),
                              "r"(bF[ni][0]), "r"(bF[ni][1]));
            }

            if (t == 8 && cc < 3) {
                __syncthreads();       // all readers done with A tile
                prodA(cc + 1);
            }
            asm volatile("cp.async.wait_group 0;" ::: "memory");
            __syncthreads();
        }
    }

    // ---------------- epilogue ----------------
    float bv[8][2];
#pragma unroll
    for (int ni = 0; ni < 8; ni++) {
        int n = n0 + ni * 8 + tig * 2;
        bv[ni][0] = bias[n];
        bv[ni][1] = bias[n + 1];
    }
#pragma unroll
    for (int mi = 0; mi < 4; mi++) {
        int r0 = m0 + mi * 16 + g;
        float* p0 = out + img + ((size_t)h * WW + (w0 + r0)) * COUT;
        float* p1 = out + img + ((size_t)h * WW + (w0 + r0 + 8)) * COUT;
#pragma unroll
        for (int ni = 0; ni < 8; ni++) {
            int n = n0 + ni * 8 + tig * 2;
            float2 v0 = make_float2(acc[mi][ni][0] + bv[ni][0],
                                    acc[mi][ni][1] + bv[ni][1]);
            float2 v1 = make_float2(acc[mi][ni][2] + bv[ni][0],
                                    acc[mi][ni][3] + bv[ni][1]);
            *(float2*)(p0 + n) = v0;
            *(float2*)(p1 + n) = v1;
        }
    }
}

extern "C" void kernel_launch(void* const* d_in, const int* in_sizes, int n_in,
                              void* d_out, int out_size) {
    (void)in_sizes; (void)n_in; (void)out_size;
    const float* x    = (const float*)d_in[0];
    const float* kern = (const float*)d_in[1];
    const float* bias = (const float*)d_in[2];
    float* out = (float*)d_out;

    wt_transform<<<(COUT * KTOT + 255) / 256, 256>>>(kern);

    cudaFuncSetAttribute(conv_mma, cudaFuncAttributeMaxDynamicSharedMemorySize, SMEM_BYTES);
    dim3 grid(WW / 128, HH, 8);   // (2, 256, 8) = 4096 CTAs, full N per CTA
    conv_mma<<<grid, 256, SMEM_BYTES>>>(x, bias, out);
}